// round 6
// baseline (speedup 1.0000x reference)
#include <cuda_runtime.h>
#include <cuda_bf16.h>
#include <cstdint>

// Problem constants
#define B_   4
#define L_   256
#define E_   256
#define K3_  768
#define NL_  6

// ---------------- scratch ----------------
__device__ __align__(16) float g_wr[589824];  // conv weights [kind][t][f][e]
__device__ __align__(16) __nv_bfloat16 g_B[(size_t)B_ * L_ * K3_];  // feat bf16

#define W2OFF 0
#define W3OFF 131072
#define W4OFF 327680

// ---------------------------------------------------------------------------
// Kernel 1: weight reformat [f][e][t] -> [kind][t][f][e], tiled transpose.
// CTA: 32f x 32e tile of one kind. Coalesced loads AND stores via smem.
// ---------------------------------------------------------------------------
__global__ __launch_bounds__(256) void reformat_w_kernel(
    const float* __restrict__ w2, const float* __restrict__ w3,
    const float* __restrict__ w4)
{
    __shared__ float sbuf[32 * 32 * 4];
    const int kind = blockIdx.y;
    const int taps = kind + 2;
    const float* __restrict__ w = (kind == 0) ? w2 : (kind == 1) ? w3 : w4;
    const int woff = (kind == 0) ? W2OFF : (kind == 1) ? W3OFF : W4OFF;
    const int f0 = (blockIdx.x >> 3) * 32;
    const int e0 = (blockIdx.x & 7) * 32;
    const int tid = threadIdx.x;

    const int n = 32 * 32 * taps;
    const int rowlen = 32 * taps;
    for (int idx = tid; idx < n; idx += 256) {
        int f = idx / rowlen;
        int within = idx - f * rowlen;
        sbuf[f * rowlen + within] = w[(size_t)(f0 + f) * 256 * taps + e0 * taps + within];
    }
    __syncthreads();
    for (int idx = tid; idx < n; idx += 256) {
        int e = idx & 31;
        int f = (idx >> 5) & 31;
        int t = idx >> 10;
        g_wr[woff + ((t * 256 + f0 + f) * 256 + e0 + e)] =
            sbuf[f * rowlen + e * taps + t];
    }
}

// ---------------------------------------------------------------------------
// Kernel 2: conv on tensor cores (tf32 m16n8k8). CTA: 64l x 32f.
// e-chunks of 32, 3-stage cp.async. Writes only g_B (bf16 feat).
// ---------------------------------------------------------------------------
#define A_STG (68 * 36)
#define W_STG (128 * 36)

__device__ __forceinline__ uint32_t f2tf(float x) {
    uint32_t u; asm("cvt.rna.tf32.f32 %0, %1;" : "=r"(u) : "f"(x)); return u;
}
__device__ __forceinline__ void mma_tf32(float* c, const uint32_t* a, const uint32_t* b) {
    asm volatile("mma.sync.aligned.m16n8k8.row.col.f32.tf32.tf32.f32 "
        "{%0,%1,%2,%3},{%4,%5,%6,%7},{%8,%9},{%0,%1,%2,%3};"
        : "+f"(c[0]), "+f"(c[1]), "+f"(c[2]), "+f"(c[3])
        : "r"(a[0]), "r"(a[1]), "r"(a[2]), "r"(a[3]), "r"(b[0]), "r"(b[1]));
}

template<int TAPS, int PAD>
__device__ __forceinline__ void conv_compute(
    const float* __restrict__ cA, const float* __restrict__ cW,
    int warpL, int warpF, int lane, float acc[2][4])
{
    #pragma unroll
    for (int t = 0; t < TAPS; t++) {
        #pragma unroll
        for (int ks = 0; ks < 4; ks++) {
            const int arow = warpL * 16 + (lane >> 2) + t + 1 - PAD;
            const int acol = ks * 8 + (lane & 3);
            uint32_t a[4];
            a[0] = f2tf(cA[arow * 36 + acol]);
            a[1] = f2tf(cA[(arow + 8) * 36 + acol]);
            a[2] = f2tf(cA[arow * 36 + acol + 4]);
            a[3] = f2tf(cA[(arow + 8) * 36 + acol + 4]);
            #pragma unroll
            for (int nf = 0; nf < 2; nf++) {
                const int brow = t * 32 + warpF * 16 + nf * 8 + (lane >> 2);
                uint32_t b[2];
                b[0] = f2tf(cW[brow * 36 + acol]);
                b[1] = f2tf(cW[brow * 36 + acol + 4]);
                mma_tf32(acc[nf], a, b);
            }
        }
    }
}

__global__ __launch_bounds__(256) void conv_tc_kernel(
    const int* __restrict__ ids, const float* __restrict__ emb,
    const float* __restrict__ b2, const float* __restrict__ b3,
    const float* __restrict__ b4)
{
    extern __shared__ __align__(16) float dsm[];
    float* sA = dsm;                 // 3 stages x 68x36
    float* sW = dsm + 3 * A_STG;     // 3 stages x 128x36
    __shared__ int   sIds[68];
    __shared__ float sBias[32];

    const int tid  = threadIdx.x;
    const int lane = tid & 31;
    const int wid  = tid >> 5;
    const int warpL = wid >> 1;
    const int warpF = wid & 1;

    const int l0   = blockIdx.x * 64;
    const int kind = blockIdx.y >> 3;
    const int ft   = blockIdx.y & 7;
    const int b    = blockIdx.z;
    const int taps = kind + 2;
    const int fbase = (kind == 0) ? 0 : (kind == 1) ? 256 : 512;
    const int woff  = (kind == 0) ? W2OFF : (kind == 1) ? W3OFF : W4OFF;
    const int kg0   = fbase + ft * 32;

    if (tid < 68) {
        int gl = l0 - 1 + tid;
        sIds[tid] = (gl >= 0 && gl < L_) ? ids[b * L_ + gl] : -1;
    }
    if (tid < 32) {
        const float* bias = (kind == 0) ? b2 : (kind == 1) ? b3 : b4;
        sBias[tid] = bias[ft * 32 + tid];
    }
    __syncthreads();

    auto load_chunk = [&](int c) {
        const int stg = c % 3;
        const int e0  = c * 32;
        float* dA = sA + stg * A_STG;
        for (int idx = tid; idx < 68 * 8; idx += 256) {
            int row = idx >> 3, q = idx & 7;
            uint32_t dst = (uint32_t)__cvta_generic_to_shared(dA + row * 36 + q * 4);
            int id = sIds[row];
            const float* src = emb + (size_t)max(id, 0) * E_ + e0 + q * 4;
            uint32_t sz = (id >= 0) ? 16u : 0u;
            asm volatile("cp.async.cg.shared.global [%0], [%1], 16, %2;"
                :: "r"(dst), "l"(src), "r"(sz));
        }
        float* dW = sW + stg * W_STG;
        for (int idx = tid; idx < taps * 32 * 8; idx += 256) {
            int row = idx >> 3, q = idx & 7;      // row = t*32 + f
            int t = row >> 5, f = row & 31;
            uint32_t dst = (uint32_t)__cvta_generic_to_shared(dW + row * 36 + q * 4);
            const float* src = g_wr + woff + ((t * 256 + ft * 32 + f) * 256 + e0 + q * 4);
            asm volatile("cp.async.cg.shared.global [%0], [%1], 16;"
                :: "r"(dst), "l"(src));
        }
        asm volatile("cp.async.commit_group;");
    };

    float acc[2][4] = {};

    load_chunk(0);
    load_chunk(1);

    for (int c = 0; c < 8; c++) {
        if (c < 7) asm volatile("cp.async.wait_group 1;");
        else       asm volatile("cp.async.wait_group 0;");
        __syncthreads();
        if (c + 2 < 8) load_chunk(c + 2);
        const float* cA = sA + (c % 3) * A_STG;
        const float* cW = sW + (c % 3) * W_STG;
        if (taps == 2)      conv_compute<2, 0>(cA, cW, warpL, warpF, lane, acc);
        else if (taps == 3) conv_compute<3, 1>(cA, cW, warpL, warpF, lane, acc);
        else                conv_compute<4, 1>(cA, cW, warpL, warpF, lane, acc);
    }

    // --- epilogue: stage C in smem, dense bf16 store of g_B ---
    __syncthreads();
    float* Cs = dsm;                 // [64][40]
    #pragma unroll
    for (int nf = 0; nf < 2; nf++) {
        const int col = warpF * 16 + nf * 8 + (lane & 3) * 2;
        #pragma unroll
        for (int half = 0; half < 2; half++) {
            const int row = warpL * 16 + (lane >> 2) + half * 8;
            *reinterpret_cast<float2*>(&Cs[row * 40 + col]) =
                make_float2(acc[nf][half * 2 + 0], acc[nf][half * 2 + 1]);
        }
    }
    __syncthreads();

    const int row = tid >> 2;
    const int c8  = (tid & 3) * 8;
    float f[8];
    *reinterpret_cast<float4*>(f)     = *reinterpret_cast<float4*>(&Cs[row * 40 + c8]);
    *reinterpret_cast<float4*>(f + 4) = *reinterpret_cast<float4*>(&Cs[row * 40 + c8 + 4]);
    __nv_bfloat162 p[4];
    #pragma unroll
    for (int q = 0; q < 4; q++)
        p[q] = __floats2bfloat162_rn(f[2 * q] + sBias[c8 + 2 * q],
                                     f[2 * q + 1] + sBias[c8 + 2 * q + 1]);
    *reinterpret_cast<uint4*>(
        &g_B[((size_t)(b * L_ + l0 + row)) * K3_ + kg0 + c8]) =
        *reinterpret_cast<uint4*>(p);
}

// ---------------------------------------------------------------------------
// Kernel 3: pair GEMM, A-fragments built on the fly.
//   C[(i*8+h), j] = sum_k feat[i,k]*w_h[k] * feat[j,k]   (h=7 is zero pad)
// CTA: 128m (16 i x 8 h) x 128n, K=768 in 24 chunks of 32, 4-stage cp.async.
// 8 warps = 4(M: wm 32) x 2(N: wn 64, 8 n8-tiles).
// ---------------------------------------------------------------------------
__device__ __forceinline__ void ldsm_x4(uint32_t* r, uint32_t addr) {
    asm volatile("ldmatrix.sync.aligned.m8n8.x4.shared.b16 {%0,%1,%2,%3}, [%4];"
        : "=r"(r[0]), "=r"(r[1]), "=r"(r[2]), "=r"(r[3]) : "r"(addr));
}
__device__ __forceinline__ void mma16816(float* c, const uint32_t* a, const uint32_t* b) {
    asm volatile("mma.sync.aligned.m16n8k16.row.col.f32.bf16.bf16.f32 "
        "{%0,%1,%2,%3}, {%4,%5,%6,%7}, {%8,%9}, {%0,%1,%2,%3};"
        : "+f"(c[0]), "+f"(c[1]), "+f"(c[2]), "+f"(c[3])
        : "r"(a[0]), "r"(a[1]), "r"(a[2]), "r"(a[3]), "r"(b[0]), "r"(b[1]));
}
__device__ __forceinline__ uint32_t mulpack(float2 v, float2 w) {
    __nv_bfloat162 r = __floats2bfloat162_rn(v.x * w.x, v.y * w.y);
    return *reinterpret_cast<uint32_t*>(&r);
}

#define SMS 40                      // B smem k-stride (bf16)
#define WT_OFF 0                    // float2[384*8] = 24,576 B
#define FI_OFF 24576                // 4 stages x 16x40x2 = 5,120 B
#define FI_STG 1280
#define BS_OFF 29696                // 4 stages x 128x40x2 = 40,960 B
#define BS_STG 10240
#define PAIR_SMEM 70656             // >= epilogue Cs 128*132*4 = 67,584

__global__ __launch_bounds__(256) void pair_mma_kernel(
    const float* __restrict__ tw, const float* __restrict__ tb,
    const float* __restrict__ sw, const float* __restrict__ sb,
    float* __restrict__ out)
{
    extern __shared__ __align__(16) char psm[];
    float2* wT = reinterpret_cast<float2*>(psm + WT_OFF);   // [384 kp][8 h]
    const uint32_t smem_u32 = (uint32_t)__cvta_generic_to_shared(psm);

    const int tid  = threadIdx.x;
    const int lane = tid & 31;
    const int wid  = tid >> 5;
    const int wm   = (wid >> 1) * 32;   // 0,32,64,96
    const int wn   = (wid & 1) * 64;    // 0,64

    const int b  = blockIdx.z;
    const int i0 = blockIdx.x * 16;     // 16 i per tile
    const int n0 = blockIdx.y * 128;

    // preload wT [kp][h] (float2 of w at k=2kp, 2kp+1)
    for (int idx = tid; idx < 3072; idx += 256) {
        int kp = idx >> 3, h = idx & 7;
        float w0, w1;
        if (h < 6)      { w0 = tw[h * K3_ + 2 * kp]; w1 = tw[h * K3_ + 2 * kp + 1]; }
        else if (h == 6){ w0 = sw[2 * kp];           w1 = sw[2 * kp + 1]; }
        else            { w0 = 0.0f; w1 = 0.0f; }
        wT[idx] = make_float2(w0, w1);
    }

    float bb[6];
    #pragma unroll
    for (int h = 0; h < 6; h++) bb[h] = tb[h];
    const float sb0 = sb[0];

    const __nv_bfloat16* gI = g_B + ((size_t)(b * L_ + i0)) * K3_;
    const __nv_bfloat16* gJ = g_B + ((size_t)(b * L_ + n0)) * K3_;

    auto load_stage = [&](int stage, int k0) {
        #pragma unroll
        for (int r = 0; r < 2; r++) {
            int idx = tid + r * 256;
            int row = idx >> 2, q = idx & 3;
            uint32_t dst = smem_u32 + BS_OFF + stage * BS_STG + (row * SMS + q * 8) * 2;
            const void* src = gJ + (size_t)row * K3_ + k0 + q * 8;
            asm volatile("cp.async.cg.shared.global [%0], [%1], 16;" :: "r"(dst), "l"(src));
        }
        if (tid < 64) {
            int row = tid >> 2, q = tid & 3;
            uint32_t dst = smem_u32 + FI_OFF + stage * FI_STG + (row * SMS + q * 8) * 2;
            const void* src = gI + (size_t)row * K3_ + k0 + q * 8;
            asm volatile("cp.async.cg.shared.global [%0], [%1], 16;" :: "r"(dst), "l"(src));
        }
        asm volatile("cp.async.commit_group;");
    };

    float acc[2][8][4] = {};

    load_stage(0, 0);
    load_stage(1, 32);
    load_stage(2, 64);
    __syncthreads();   // wT visible to all

    const int q = lane & 3;
    const int h = lane >> 2;
    const int ib0 = wm >> 3;

    for (int it = 0; it < 24; it++) {
        if (it < 22)       asm volatile("cp.async.wait_group 2;");
        else if (it == 22) asm volatile("cp.async.wait_group 1;");
        else               asm volatile("cp.async.wait_group 0;");
        __syncthreads();

        if (it + 3 < 24) load_stage((it + 3) & 3, (it + 3) * 32);

        const int st = it & 3;
        const int k0 = it * 32;
        const __nv_bfloat162* fI = reinterpret_cast<const __nv_bfloat162*>(
            psm + FI_OFF + st * FI_STG);
        const uint32_t bBase = smem_u32 + BS_OFF + st * BS_STG;

        #pragma unroll
        for (int ks = 0; ks < 32; ks += 16) {
            const int kq  = (ks >> 1) + q;                 // fI col (pairs)
            const int kpg = ((k0 + ks) >> 1) + q;          // global pair idx
            const float2 wlo = wT[kpg * 8 + h];
            const float2 whi = wT[(kpg + 4) * 8 + h];

            uint32_t a[2][4];
            #pragma unroll
            for (int fm = 0; fm < 2; fm++) {
                const int ib = ib0 + fm * 2;
                float2 v00 = __bfloat1622float2(fI[ib * 20 + kq]);
                float2 v10 = __bfloat1622float2(fI[(ib + 1) * 20 + kq]);
                float2 v01 = __bfloat1622float2(fI[ib * 20 + kq + 4]);
                float2 v11 = __bfloat1622float2(fI[(ib + 1) * 20 + kq + 4]);
                a[fm][0] = mulpack(v00, wlo);
                a[fm][1] = mulpack(v10, wlo);
                a[fm][2] = mulpack(v01, whi);
                a[fm][3] = mulpack(v11, whi);
            }

            uint32_t bf[8][2];
            const int p    = lane >> 4;
            const int half = (lane >> 3) & 1;
            #pragma unroll
            for (int fp = 0; fp < 4; fp++) {
                const int brow = wn + fp * 16 + p * 8 + (lane & 7);
                uint32_t r4[4];
                ldsm_x4(r4, bBase + (brow * SMS + ks + half * 8) * 2);
                bf[fp * 2][0] = r4[0]; bf[fp * 2][1] = r4[1];
                bf[fp * 2 + 1][0] = r4[2]; bf[fp * 2 + 1][1] = r4[3];
            }

            #pragma unroll
            for (int fm = 0; fm < 2; fm++)
                #pragma unroll
                for (int fn = 0; fn < 8; fn++)
                    mma16816(acc[fm][fn], a[fm], bf[fn]);
        }
    }

    // --- epilogue: stage full C tile [128][132] in smem ---
    __syncthreads();
    float* Cs = reinterpret_cast<float*>(psm);
    #pragma unroll
    for (int fm = 0; fm < 2; fm++) {
        const int r0 = wm + fm * 16 + (lane >> 2);
        #pragma unroll
        for (int fn = 0; fn < 8; fn++) {
            const int c0 = wn + fn * 8 + (lane & 3) * 2;
            *reinterpret_cast<float2*>(&Cs[r0 * 132 + c0]) =
                make_float2(acc[fm][fn][0], acc[fm][fn][1]);
            *reinterpret_cast<float2*>(&Cs[(r0 + 8) * 132 + c0]) =
                make_float2(acc[fm][fn][2], acc[fm][fn][3]);
        }
    }
    __syncthreads();

    // triple logits: 16 il x 128 j x 6 h = 3072 float4, 12 per thread
    #pragma unroll
    for (int r = 0; r < 12; r++) {
        const int fidx = tid + r * 256;           // float4 index
        const int il = fidx / 192;
        const int o  = (fidx - il * 192) * 4;     // float offset in row
        float4 v;
        {
            int o0 = o;     int j = o0 / 6, hh = o0 - j * 6; v.x = Cs[(il * 8 + hh) * 132 + j] + bb[hh];
        }
        {
            int o1 = o + 1; int j = o1 / 6, hh = o1 - j * 6; v.y = Cs[(il * 8 + hh) * 132 + j] + bb[hh];
        }
        {
            int o2 = o + 2; int j = o2 / 6, hh = o2 - j * 6; v.z = Cs[(il * 8 + hh) * 132 + j] + bb[hh];
        }
        {
            int o3 = o + 3; int j = o3 / 6, hh = o3 - j * 6; v.w = Cs[(il * 8 + hh) * 132 + j] + bb[hh];
        }
        *reinterpret_cast<float4*>(
            out + ((size_t)((b * L_ + i0 + il) * L_ + n0)) * NL_ + o) = v;
    }

    // scores: 16 il x 128 j = 512 float4, 2 per thread
    {
        float* sc = out + (size_t)B_ * L_ * L_ * NL_;
        #pragma unroll
        for (int r = 0; r < 2; r++) {
            const int fidx = tid + r * 256;       // 0..511
            const int il = fidx >> 5;
            const int j4 = (fidx & 31) * 4;
            float4 v = *reinterpret_cast<float4*>(&Cs[(il * 8 + 6) * 132 + j4]);
            v.x += sb0; v.y += sb0; v.z += sb0; v.w += sb0;
            *reinterpret_cast<float4*>(
                sc + (size_t)(b * L_ + i0 + il) * L_ + n0 + j4) = v;
        }
    }
}

// ---------------------------------------------------------------------------
extern "C" void kernel_launch(void* const* d_in, const int* in_sizes, int n_in,
                              void* d_out, int out_size) {
    const int*   ids = (const int*)  d_in[0];
    const float* emb = (const float*)d_in[1];
    const float* w2  = (const float*)d_in[2];
    const float* b2  = (const float*)d_in[3];
    const float* w3  = (const float*)d_in[4];
    const float* b3  = (const float*)d_in[5];
    const float* w4  = (const float*)d_in[6];
    const float* b4  = (const float*)d_in[7];
    const float* tw  = (const float*)d_in[8];
    const float* tb  = (const float*)d_in[9];
    const float* sw  = (const float*)d_in[10];
    const float* sb  = (const float*)d_in[11];
    float* out = (float*)d_out;

    const int conv_smem = 3 * (A_STG + W_STG) * 4;   // 84,672 B
    cudaFuncSetAttribute(conv_tc_kernel,
        cudaFuncAttributeMaxDynamicSharedMemorySize, conv_smem);
    cudaFuncSetAttribute(pair_mma_kernel,
        cudaFuncAttributeMaxDynamicSharedMemorySize, PAIR_SMEM);

    dim3 rgrid(64, 3);
    reformat_w_kernel<<<rgrid, 256>>>(w2, w3, w4);

    dim3 cgrid(4, 24, 4);
    conv_tc_kernel<<<cgrid, 256, conv_smem>>>(ids, emb, b2, b3, b4);

    dim3 pgrid(16, 2, 4);   // 128 CTAs
    pair_mma_kernel<<<pgrid, 256, PAIR_SMEM>>>(tw, tb, sw, sb, out);
}